// round 13
// baseline (speedup 1.0000x reference)
#include <cuda_runtime.h>
#include <cuda_bf16.h>

#define NB   8
#define NA   65536
#define NC   80
#define NG   16
#define NTOP 50

// ---------------- global scratch (no allocations allowed) ----------------
__device__ unsigned int g_t2bits[NB * NG];
__device__ float        g_inv[NB * NG];
__device__ double       g_pos;
__device__ double       g_neg;

// ---------------- init (reruns on every graph replay) ----------------
__global__ void k_init() {
    int t = threadIdx.x;
    if (t < NB * NG) g_t2bits[t] = 0u;
    if (t == 0) { g_pos = 0.0; g_neg = 0.0; }
}

// ---------------- kernel 1: per-(b,g) max IoU of decoded boxes ----------------
__global__ void __launch_bounds__(256) k_maxiou(
    const float4* __restrict__ breg,
    const float4* __restrict__ anc,
    const float4* __restrict__ tbx)
{
    __shared__ float4 s_tb[NG];
    __shared__ float  s_ta[NG];
    __shared__ float  s_m[NG][8];
    int tid = threadIdx.x;
    int b = blockIdx.x >> 8;                 // 8 * 256 blocks
    int a = ((blockIdx.x & 255) << 8) | tid;

    if (tid < NG) {
        float4 tb = tbx[b * NG + tid];
        s_tb[tid] = tb;
        s_ta[tid] = (tb.z - tb.x) * (tb.w - tb.y);
    }
    __syncthreads();

    float4 r  = breg[b * NA + a];
    float4 an = anc[a];
    float w  = an.z * __expf(r.z * 0.2f);
    float h  = an.w * __expf(r.w * 0.2f);
    float cx = fmaf(r.x * 0.1f, an.z, an.x);
    float cy = fmaf(r.y * 0.1f, an.w, an.y);
    float x1 = cx - 0.5f * w, y1 = cy - 0.5f * h;
    float x2 = cx + 0.5f * w, y2 = cy + 0.5f * h;
    float ad = (x2 - x1) * (y2 - y1);

    int lane = tid & 31, wid = tid >> 5;
    #pragma unroll
    for (int g = 0; g < NG; g++) {
        float4 tb = s_tb[g];
        float lx = fmaxf(tb.x, x1), ly = fmaxf(tb.y, y1);
        float rx = fminf(tb.z, x2), ry = fminf(tb.w, y2);
        float iw = fmaxf(rx - lx, 0.f), ih = fmaxf(ry - ly, 0.f);
        float inter = iw * ih;
        float iou = __fdividef(inter, s_ta[g] + ad - inter);
        #pragma unroll
        for (int o = 16; o > 0; o >>= 1)
            iou = fmaxf(iou, __shfl_down_sync(0xffffffffu, iou, o));
        if (lane == 0) s_m[g][wid] = iou;
    }
    __syncthreads();
    if (tid < NG) {
        float m = s_m[tid][0];
        #pragma unroll
        for (int i = 1; i < 8; i++) m = fmaxf(m, s_m[tid][i]);
        atomicMax(&g_t2bits[b * NG + tid], __float_as_uint(m)); // iou >= 0: bits monotone
    }
}

// ---------------- kernel 2: t2 -> reciprocal ----------------
__global__ void k_t2() {
    int t = threadIdx.x;
    if (t < NB * NG) {
        // BBOX_T + 1e-12 rounds to 0.5f in fp32
        float t2 = fmaxf(__uint_as_float(g_t2bits[t]), 0.5f);
        g_inv[t] = 1.0f / (t2 - 0.5f);       // +inf allowed; obp clamp absorbs it
    }
}

// ---------------- top-k helpers ----------------
__device__ __forceinline__ unsigned long long mqm_key(
    const float4* __restrict__ anc, int a, float4 tb, float ta)
{
    float4 an = __ldg(&anc[a]);
    float ax1 = an.x - 0.5f * an.z, ay1 = an.y - 0.5f * an.w;
    float ax2 = an.x + 0.5f * an.z, ay2 = an.y + 0.5f * an.w;
    float lx = fmaxf(tb.x, ax1), ly = fmaxf(tb.y, ay1);
    float rx = fminf(tb.z, ax2), ry = fminf(tb.w, ay2);
    float iw = fmaxf(rx - lx, 0.f), ih = fmaxf(ry - ly, 0.f);
    float inter = iw * ih;
    float aa = (ax2 - ax1) * (ay2 - ay1);
    float iou = __fdividef(inter, ta + aa - inter);
    // value descending, then lowest index first (matches jax.lax.top_k)
    return ((unsigned long long)__float_as_uint(iou) << 32)
         | (unsigned long long)(0xffffffffu - (unsigned)a);
}

__device__ __forceinline__ void ins8(unsigned long long (&top)[8], unsigned long long key) {
    if (key > top[7]) {
        #pragma unroll
        for (int i = 0; i < 8; i++) {
            unsigned long long hi = (key > top[i]) ? key : top[i];
            unsigned long long lo = (key > top[i]) ? top[i] : key;
            top[i] = hi; key = lo;
        }
    }
}

__device__ __forceinline__ float sl1f(float v) {
    float av = fabsf(v);
    return (av < 0.11f) ? (0.5f / 0.11f) * v * v : av - 0.055f;
}

// ---------------- kernel 3: top-50 + positive bag loss (one block per (b,g)) ----------------
__global__ void __launch_bounds__(1024) k_pos(
    const float*  __restrict__ breg,
    const float*  __restrict__ logits,
    const float4* __restrict__ anc,
    const float4* __restrict__ tbx,
    const int*    __restrict__ lbl)
{
    __shared__ unsigned long long s_red[32];
    __shared__ unsigned long long s_win;
    __shared__ int   s_sel[NTOP];
    __shared__ float s_wv[NTOP], s_wl[NTOP];

    int tid = threadIdx.x;
    int b = blockIdx.x >> 4;     // 128 blocks = 8*16
    int g = blockIdx.x & 15;

    float4 tb = tbx[b * NG + g];
    float ta = (tb.z - tb.x) * (tb.w - tb.y);

    unsigned long long top[8];
    #pragma unroll
    for (int i = 0; i < 8; i++) top[i] = 0ull;

    // phase 1: each thread scans 64 anchors (coalesced), keeps sorted top-8
    for (int i = 0; i < 64; i++) {
        int a = i * 1024 + tid;
        ins8(top, mqm_key(anc, a, tb, ta));
    }

    // phase 2: 50 rounds of block argmax with owner-pop + threshold refill
    unsigned long long thr = 0xffffffffffffffffULL;
    bool popped = false;
    for (int r = 0; r < NTOP; r++) {
        if (top[0] == 0ull && popped) {
            // refill: re-scan own anchors, keep keys strictly below last popped
            for (int i = 0; i < 64; i++) {
                unsigned long long k = mqm_key(anc, i * 1024 + tid, tb, ta);
                if (k < thr) ins8(top, k);
            }
        }
        unsigned long long m = top[0];
        #pragma unroll
        for (int o = 16; o > 0; o >>= 1) {
            unsigned long long o2 = __shfl_down_sync(0xffffffffu, m, o);
            if (o2 > m) m = o2;
        }
        if ((tid & 31) == 0) s_red[tid >> 5] = m;
        __syncthreads();
        if (tid < 32) {
            unsigned long long v = s_red[tid];
            #pragma unroll
            for (int o = 16; o > 0; o >>= 1) {
                unsigned long long o2 = __shfl_down_sync(0xffffffffu, v, o);
                if (o2 > v) v = o2;
            }
            if (tid == 0) s_win = v;
        }
        __syncthreads();
        unsigned long long win = s_win;
        if (top[0] == win) {    // keys unique -> exactly one winner
            s_sel[r] = (int)(0xffffffffu - (unsigned)(win & 0xffffffffu));
            thr = win;
            popped = true;
            #pragma unroll
            for (int i = 0; i < 7; i++) top[i] = top[i + 1];
            top[7] = 0ull;
        }
        // no extra barrier needed: next round's s_red/s_win writes sit behind
        // the next __syncthreads(); s_sel is only read after the final barrier.
    }
    __syncthreads();

    // phase 3: positive bag loss over the 50 selected anchors
    if (tid < NTOP) {
        int a = s_sel[tid];
        int c = lbl[b * NG + g];
        float l = logits[((long long)(b * NA + a)) * NC + c];
        float p = __fdividef(1.f, 1.f + __expf(-l));

        float4 an = __ldg(&anc[a]);
        const float4 br = ((const float4*)breg)[b * NA + a];
        float tcx = 0.5f * (tb.x + tb.z), tcy = 0.5f * (tb.y + tb.w);
        float tw = tb.z - tb.x, th = tb.w - tb.y;
        float gx = __fdividef(tcx - an.x, 0.1f * an.z);
        float gy = __fdividef(tcy - an.y, 0.1f * an.w);
        float gw = __logf(__fdividef(tw, an.z)) * 5.0f;   // / VAR1(=0.2)
        float gh = __logf(__fdividef(th, an.w)) * 5.0f;

        float s = sl1f(gx - br.x) + sl1f(gy - br.y) + sl1f(gw - br.z) + sl1f(gh - br.w);
        float bp = __expf(-0.75f * s);
        float lg = p * bp;
        float w = __fdividef(1.f, fmaxf(1.f - lg, 1e-12f));
        s_wv[tid] = w;
        s_wl[tid] = w * lg;
    }
    __syncthreads();
    if (tid == 0) {
        float sw = 0.f, sl = 0.f;
        #pragma unroll
        for (int k = 0; k < NTOP; k++) { sw += s_wv[k]; sl += s_wl[k]; }
        float pos = -__logf(__fdividef(sl, sw));
        atomicAdd(&g_pos, (double)pos);
    }
}

// ---------------- kernel 4: negative focal loss (dominant cost) ----------------
__global__ void __launch_bounds__(256) k_neg(
    const float4* __restrict__ breg,
    const float*  __restrict__ logits,
    const float4* __restrict__ anc,
    const float4* __restrict__ tbx,
    const int*    __restrict__ lbl)
{
    __shared__ float  s_log[256 * 17];      // 16-class chunk, pad 17 vs bank conflicts
    __shared__ float  s_obp[NG * 256];      // [g][anchor-in-block]
    __shared__ float4 s_tb[NG];
    __shared__ float  s_ta[NG], s_inv[NG];
    __shared__ unsigned int s_cm[NC];       // per-class label bitmask over g
    __shared__ float  s_r2[8];

    int tid = threadIdx.x;
    int b  = blockIdx.x >> 8;
    int a0 = (blockIdx.x & 255) << 8;
    int a  = a0 + tid;

    if (tid < NG) {
        float4 tb = tbx[b * NG + tid];
        s_tb[tid]  = tb;
        s_ta[tid]  = (tb.z - tb.x) * (tb.w - tb.y);
        s_inv[tid] = g_inv[b * NG + tid];
    }
    if (tid < NC) {
        unsigned m = 0;
        #pragma unroll
        for (int g = 0; g < NG; g++)
            if (lbl[b * NG + g] == tid) m |= (1u << g);
        s_cm[tid] = m;
    }
    __syncthreads();

    // decode this anchor's box, obp against the 16 gt boxes
    {
        float4 r  = breg[b * NA + a];
        float4 an = anc[a];
        float w  = an.z * __expf(r.z * 0.2f);
        float h  = an.w * __expf(r.w * 0.2f);
        float cx = fmaf(r.x * 0.1f, an.z, an.x);
        float cy = fmaf(r.y * 0.1f, an.w, an.y);
        float x1 = cx - 0.5f * w, y1 = cy - 0.5f * h;
        float x2 = cx + 0.5f * w, y2 = cy + 0.5f * h;
        float ad = (x2 - x1) * (y2 - y1);
        #pragma unroll
        for (int g = 0; g < NG; g++) {
            float4 tb = s_tb[g];
            float lx = fmaxf(tb.x, x1), ly = fmaxf(tb.y, y1);
            float rx = fminf(tb.z, x2), ry = fminf(tb.w, y2);
            float iw = fmaxf(rx - lx, 0.f), ih = fmaxf(ry - ly, 0.f);
            float inter = iw * ih;
            float iou = __fdividef(inter, s_ta[g] + ad - inter);
            float o = (iou - 0.5f) * s_inv[g];
            o = fminf(fmaxf(o, 0.f), 1.f);  // fmaxf(NaN,0)=0 handles inv=+inf edge
            s_obp[g * 256 + tid] = o;
        }
    }

    float acc = 0.f;
    const float* lbase = logits + ((long long)(b * NA + a0)) * NC;

    #pragma unroll 1
    for (int c0 = 0; c0 < NC; c0 += 16) {
        __syncthreads();
        // coalesced staged load of 256 anchors x 16 classes (1024 float4)
        #pragma unroll
        for (int j = 0; j < 4; j++) {
            int q = tid + j * 256;
            int row = q >> 2, quad = q & 3;
            float4 v = *(const float4*)(lbase + row * NC + c0 + quad * 4);
            int so = row * 17 + quad * 4;
            s_log[so]     = v.x;
            s_log[so + 1] = v.y;
            s_log[so + 2] = v.z;
            s_log[so + 3] = v.w;
        }
        __syncthreads();

        #pragma unroll
        for (int c = 0; c < 16; c++) {
            float l = s_log[tid * 17 + c];
            unsigned m = s_cm[c0 + c];
            float bp = 0.f;
            while (m) {                       // avg 0.2 iterations (16 labels / 80 classes)
                int g = __ffs(m) - 1; m &= m - 1;
                bp = fmaxf(bp, s_obp[g * 256 + tid]);
            }
            float p = __fdividef(1.f, 1.f + __expf(-l));
            float x = p * (1.f - bp);
            acc += x * x * (-__logf(1.f - x));
        }
    }

    // block reduce, one double atomic per block
    #pragma unroll
    for (int o = 16; o > 0; o >>= 1) acc += __shfl_down_sync(0xffffffffu, acc, o);
    if ((tid & 31) == 0) s_r2[tid >> 5] = acc;
    __syncthreads();
    if (tid == 0) {
        float s = 0.f;
        #pragma unroll
        for (int i = 0; i < 8; i++) s += s_r2[i];
        atomicAdd(&g_neg, (double)s);
    }
}

// ---------------- finalize ----------------
__global__ void k_final(float* __restrict__ out) {
    // positive_loss * ALPHA, negative_loss * (1-ALPHA); n_pos = 128
    out[0] = (float)(g_pos / 128.0 * 0.5);
    out[1] = (float)(g_neg / 6400.0 * 0.5);
}

extern "C" void kernel_launch(void* const* d_in, const int* in_sizes, int n_in,
                              void* d_out, int out_size) {
    const float4* breg   = (const float4*)d_in[0];  // (B,A,4)
    const float*  logits = (const float*) d_in[1];  // (B,A,C)
    const float4* anc    = (const float4*)d_in[2];  // (A,4) cxcywh
    const float4* tbx    = (const float4*)d_in[3];  // (B,G,4) corners
    const int*    lbl    = (const int*)   d_in[4];  // (B,G)
    float* out = (float*)d_out;
    (void)in_sizes; (void)n_in; (void)out_size;

    k_init  <<<1, 128>>>();
    k_maxiou<<<NB * 256, 256>>>(breg, anc, tbx);
    k_t2    <<<1, 128>>>();
    k_pos   <<<NB * NG, 1024>>>((const float*)d_in[0], logits, anc, tbx, lbl);
    k_neg   <<<NB * 256, 256>>>(breg, logits, anc, tbx, lbl);
    k_final <<<1, 1>>>(out);
}